// round 17
// baseline (speedup 1.0000x reference)
#include <cuda_runtime.h>
#include <cuda_bf16.h>
#include <math_constants.h>
#include <mma.h>

using namespace nvcuda;

// Problem constants
#define NQ   2048
#define NK   100000
#define NKP  100096          // padded to multiple of 128 (n-tile)
#define DIM  128
#define KSEL 50
#define DELTA 1e-3f
#define EPS  0.5f            // candidate margin >> dot2 approx error (max ~0.15)

#define NTHR  4096           // threshold sample width (first keys)
#define CANDW 4096           // per-query candidate list width

// Scratch (device globals: allocation-free rule)
__device__ float g_Dthr[(size_t)NQ * NTHR];          // thr-pass raw dots (32 MB)
__device__ unsigned long long g_cand[(size_t)NQ * CANDW];  // 64 MB
__device__ int   g_cnt[NQ];
__device__ float g_qn[NQ];
__device__ float g_kn[NKP];
__device__ float g_thr[NQ];
__device__ __nv_bfloat16 g_Qh[(size_t)NQ * DIM];
__device__ __nv_bfloat16 g_Kh[(size_t)NKP * DIM];
__device__ __nv_bfloat16 g_Kl[(size_t)NKP * DIM];

// ---------------------------------------------------------------------------
// K1: row norms, XLA:CPU strict reduce semantics: serial scalar chain in index
// order, multiply then add, NO fma. One thread per row. (Bit-exact, load-bearing.)
// ---------------------------------------------------------------------------
__global__ __launch_bounds__(256) void norms_kernel(
    const float* __restrict__ Q, const float* __restrict__ Kk)
{
    int i = blockIdx.x * blockDim.x + threadIdx.x;
    if (i >= NQ + NKP) return;

    const float* row;
    float* dst;
    if (i < NQ) {
        row = Q + (size_t)i * DIM;
        dst = &g_qn[i];
    } else {
        int n = i - NQ;
        if (n >= NK) { g_kn[n] = CUDART_INF_F; return; }
        row = Kk + (size_t)n * DIM;
        dst = &g_kn[n];
    }

    float acc = 0.f;
    const float4* r4 = reinterpret_cast<const float4*>(row);
    #pragma unroll 8
    for (int j = 0; j < DIM / 4; j++) {
        float4 v = __ldg(r4 + j);
        acc = __fadd_rn(acc, __fmul_rn(v.x, v.x));
        acc = __fadd_rn(acc, __fmul_rn(v.y, v.y));
        acc = __fadd_rn(acc, __fmul_rn(v.z, v.z));
        acc = __fadd_rn(acc, __fmul_rn(v.w, v.w));
    }
    *dst = acc;
}

// ---------------------------------------------------------------------------
// K1b: bf16 split. Q -> hi only; K -> hi + lo (dot2 = Qh.Kh + Qh.Kl).
// Also zeroes the per-query candidate counters (graph-replay safe).
// ---------------------------------------------------------------------------
__global__ __launch_bounds__(256) void prep_kernel(
    const float* __restrict__ Q, const float* __restrict__ Kk)
{
    size_t i = (size_t)blockIdx.x * blockDim.x + threadIdx.x;
    if (i < NQ) g_cnt[i] = 0;

    const size_t nq_elems = (size_t)NQ * DIM;
    const size_t total = nq_elems + (size_t)NKP * DIM;
    if (i >= total) return;

    if (i < nq_elems) {
        g_Qh[i] = __float2bfloat16(Q[i]);
    } else {
        size_t j = i - nq_elems;
        size_t n = j >> 7;
        float x = (n < NK) ? Kk[j] : 0.f;
        __nv_bfloat16 hi = __float2bfloat16(x);
        float lo = x - __bfloat162float(hi);
        g_Kh[j] = hi;
        g_Kl[j] = __float2bfloat16(lo);
    }
}

// ---------------------------------------------------------------------------
// Shared GEMM mainloop config: 128x128 CTA tile, 8 warps (2m x 4n),
// dot2 = Qh.Kh + Qh.Kl (fp32 accum).
// ---------------------------------------------------------------------------
#define GLD 40   // smem leading dim (bf16 elems), multiple of 8

// K2a: thr-pass GEMM over first NTHR keys, writes raw dots to g_Dthr.
__global__ __launch_bounds__(256) void gemm_thr_kernel()
{
    __shared__ __nv_bfloat16 Ah[128 * GLD];
    __shared__ __nv_bfloat16 Bh[128 * GLD];
    __shared__ __nv_bfloat16 Bl[128 * GLD];

    const int tid  = threadIdx.x;
    const int warp = tid >> 5;
    const int bm = blockIdx.y * 128;
    const int bn = blockIdx.x * 128;
    const int wm = (warp & 1) * 64;
    const int wn = (warp >> 1) * 32;

    wmma::fragment<wmma::accumulator, 16, 16, 16, float> acc[4][2];
    #pragma unroll
    for (int i = 0; i < 4; i++)
        #pragma unroll
        for (int j = 0; j < 2; j++)
            wmma::fill_fragment(acc[i][j], 0.f);

    #pragma unroll 1
    for (int kc = 0; kc < DIM; kc += 32) {
        #pragma unroll
        for (int it = 0; it < 4; it++) {
            int s  = tid + it * 256;
            int r  = s >> 3;
            int kq = (s & 7) << 2;
            size_t qo = (size_t)(bm + r) * DIM + kc + kq;
            size_t ko = (size_t)(bn + r) * DIM + kc + kq;
            *reinterpret_cast<uint2*>(&Ah[r * GLD + kq]) =
                *reinterpret_cast<const uint2*>(&g_Qh[qo]);
            *reinterpret_cast<uint2*>(&Bh[r * GLD + kq]) =
                *reinterpret_cast<const uint2*>(&g_Kh[ko]);
            *reinterpret_cast<uint2*>(&Bl[r * GLD + kq]) =
                *reinterpret_cast<const uint2*>(&g_Kl[ko]);
        }
        __syncthreads();

        #pragma unroll
        for (int kk = 0; kk < 32; kk += 16) {
            wmma::fragment<wmma::matrix_a, 16, 16, 16, __nv_bfloat16, wmma::row_major> ah[4];
            wmma::fragment<wmma::matrix_b, 16, 16, 16, __nv_bfloat16, wmma::col_major> bh[2], bl[2];
            #pragma unroll
            for (int i = 0; i < 4; i++)
                wmma::load_matrix_sync(ah[i], &Ah[(wm + i * 16) * GLD + kk], GLD);
            #pragma unroll
            for (int j = 0; j < 2; j++) {
                wmma::load_matrix_sync(bh[j], &Bh[(wn + j * 16) * GLD + kk], GLD);
                wmma::load_matrix_sync(bl[j], &Bl[(wn + j * 16) * GLD + kk], GLD);
            }
            #pragma unroll
            for (int i = 0; i < 4; i++)
                #pragma unroll
                for (int j = 0; j < 2; j++) {
                    wmma::mma_sync(acc[i][j], ah[i], bh[j], acc[i][j]);
                    wmma::mma_sync(acc[i][j], ah[i], bl[j], acc[i][j]);
                }
        }
        __syncthreads();
    }

    #pragma unroll
    for (int i = 0; i < 4; i++)
        #pragma unroll
        for (int j = 0; j < 2; j++)
            wmma::store_matrix_sync(
                g_Dthr + (size_t)(bm + wm + i * 16) * NTHR + (bn + wn + j * 16),
                acc[i][j], NTHR, wmma::mem_row_major);
}

// ---------------------------------------------------------------------------
// K2b: per-query fixed threshold from the NTHR-key sample (same as R15).
// 64th smallest of 256 per-thread minima -> F(thr)~1.7% -> ~1780 keeps,
// and always >= 64 sample keys pass.
// ---------------------------------------------------------------------------
__global__ __launch_bounds__(256) void thr_kernel()
{
    __shared__ unsigned mins[256];
    const int q   = blockIdx.x;
    const int tid = threadIdx.x;
    const float qn = g_qn[q];

    const float* Drow = g_Dthr + (size_t)q * NTHR;
    float m = CUDART_INF_F;
    #pragma unroll
    for (int t = 0; t < NTHR / 256; t++) {
        int i = tid + t * 256;
        float d = qn - 2.f * Drow[i] + g_kn[i];
        m = fminf(m, d);
    }
    mins[tid] = __float_as_uint(m);
    __syncthreads();

    for (int k = 2; k <= 256; k <<= 1) {
        for (int j = k >> 1; j > 0; j >>= 1) {
            int ixj = tid ^ j;
            if (ixj > tid) {
                bool up = ((tid & k) == 0);
                unsigned a = mins[tid], b = mins[ixj];
                if ((a > b) == up) { mins[tid] = b; mins[ixj] = a; }
            }
            __syncthreads();
        }
    }
    if (tid == 0) g_thr[q] = __uint_as_float(mins[63]);
}

// ---------------------------------------------------------------------------
// K2c: MAIN fused GEMM + filter. Same mainloop; epilogue stages each warp's
// 16x32 accumulator block through per-warp smem, computes d = qn - 2*dot + kn,
// and pushes d <= thr[m] candidates into per-query global lists. No D matrix.
// Padded cols: kn=+INF -> never pass.
// ---------------------------------------------------------------------------
__global__ __launch_bounds__(256) void gemm_filter_kernel()
{
    __shared__ __nv_bfloat16 Ah[128 * GLD];          // 10240 B
    __shared__ __nv_bfloat16 Bh[128 * GLD];
    __shared__ __nv_bfloat16 Bl[128 * GLD];
    __shared__ float stage[8][16 * 32];              // 16384 B (per-warp 16x32)
    __shared__ float s_qn[128], s_kn[128], s_thr[128];

    const int tid  = threadIdx.x;
    const int warp = tid >> 5;
    const int lane = tid & 31;
    const int bm = blockIdx.y * 128;
    const int bn = blockIdx.x * 128;
    const int wm = (warp & 1) * 64;
    const int wn = (warp >> 1) * 32;

    if (tid < 128) {
        s_qn[tid]  = g_qn[bm + tid];
        s_thr[tid] = g_thr[bm + tid];
    } else {
        int t = tid - 128;
        s_kn[t] = g_kn[bn + t];
    }

    wmma::fragment<wmma::accumulator, 16, 16, 16, float> acc[4][2];
    #pragma unroll
    for (int i = 0; i < 4; i++)
        #pragma unroll
        for (int j = 0; j < 2; j++)
            wmma::fill_fragment(acc[i][j], 0.f);

    #pragma unroll 1
    for (int kc = 0; kc < DIM; kc += 32) {
        #pragma unroll
        for (int it = 0; it < 4; it++) {
            int s  = tid + it * 256;
            int r  = s >> 3;
            int kq = (s & 7) << 2;
            size_t qo = (size_t)(bm + r) * DIM + kc + kq;
            size_t ko = (size_t)(bn + r) * DIM + kc + kq;
            *reinterpret_cast<uint2*>(&Ah[r * GLD + kq]) =
                *reinterpret_cast<const uint2*>(&g_Qh[qo]);
            *reinterpret_cast<uint2*>(&Bh[r * GLD + kq]) =
                *reinterpret_cast<const uint2*>(&g_Kh[ko]);
            *reinterpret_cast<uint2*>(&Bl[r * GLD + kq]) =
                *reinterpret_cast<const uint2*>(&g_Kl[ko]);
        }
        __syncthreads();

        #pragma unroll
        for (int kk = 0; kk < 32; kk += 16) {
            wmma::fragment<wmma::matrix_a, 16, 16, 16, __nv_bfloat16, wmma::row_major> ah[4];
            wmma::fragment<wmma::matrix_b, 16, 16, 16, __nv_bfloat16, wmma::col_major> bh[2], bl[2];
            #pragma unroll
            for (int i = 0; i < 4; i++)
                wmma::load_matrix_sync(ah[i], &Ah[(wm + i * 16) * GLD + kk], GLD);
            #pragma unroll
            for (int j = 0; j < 2; j++) {
                wmma::load_matrix_sync(bh[j], &Bh[(wn + j * 16) * GLD + kk], GLD);
                wmma::load_matrix_sync(bl[j], &Bl[(wn + j * 16) * GLD + kk], GLD);
            }
            #pragma unroll
            for (int i = 0; i < 4; i++)
                #pragma unroll
                for (int j = 0; j < 2; j++) {
                    wmma::mma_sync(acc[i][j], ah[i], bh[j], acc[i][j]);
                    wmma::mma_sync(acc[i][j], ah[i], bl[j], acc[i][j]);
                }
        }
        __syncthreads();
    }

    // Epilogue: per-warp staging + filter + push. Lane l owns row (l>>1),
    // cols (l&1)*16 + [0,16) of its warp's 16x32 block.
    const int srow = lane >> 1;
    const int scol = (lane & 1) * 16;
    #pragma unroll
    for (int i = 0; i < 4; i++) {
        wmma::store_matrix_sync(&stage[warp][0],  acc[i][0], 32, wmma::mem_row_major);
        wmma::store_matrix_sync(&stage[warp][16], acc[i][1], 32, wmma::mem_row_major);
        __syncwarp();

        const int ml  = wm + i * 16 + srow;     // local m row 0..127
        const int gm  = bm + ml;
        const float qn  = s_qn[ml];
        const float thr = s_thr[ml];
        #pragma unroll
        for (int t = 0; t < 16; t++) {
            const int nl = wn + scol + t;       // local n col 0..127
            float dot = stage[warp][srow * 32 + scol + t];
            float d = qn - 2.f * dot + s_kn[nl];
            if (d <= thr) {
                int p = atomicAdd(&g_cnt[gm], 1);
                if (p < CANDW)
                    g_cand[(size_t)gm * CANDW + p] =
                        ((unsigned long long)__float_as_uint(d) << 32)
                        | (unsigned)(bn + nl);
            }
        }
        __syncwarp();
    }
}

// ---------------------------------------------------------------------------
// K3: per-query: load candidate list, sort, EPS cut, exact bit-identical
// rescore (serial __fmaf_rn chain, reference association), fp64 weights.
// ---------------------------------------------------------------------------
#define BUF 4096
#define MMAX 256

__device__ __forceinline__ void bitonic_sort_buf(unsigned long long* keys, int tid)
{
    for (int k = 2; k <= BUF; k <<= 1) {
        for (int j = k >> 1; j > 0; j >>= 1) {
            #pragma unroll
            for (int t = 0; t < BUF / 256; t++) {
                int i = tid + t * 256;
                int ixj = i ^ j;
                if (ixj > i) {
                    bool up = ((i & k) == 0);
                    unsigned long long a = keys[i], b = keys[ixj];
                    if ((a > b) == up) { keys[i] = b; keys[ixj] = a; }
                }
            }
            __syncthreads();
        }
    }
}

__device__ __forceinline__ void bitonic_sort256(unsigned long long* keys, int tid)
{
    for (int k = 2; k <= 256; k <<= 1) {
        for (int j = k >> 1; j > 0; j >>= 1) {
            int ixj = tid ^ j;
            if (ixj > tid) {
                bool up = ((tid & k) == 0);
                unsigned long long a = keys[tid], b = keys[ixj];
                if ((a > b) == up) { keys[tid] = b; keys[ixj] = a; }
            }
            __syncthreads();
        }
    }
}

__global__ __launch_bounds__(256) void select_kernel(
    const float* __restrict__ Q, const float* __restrict__ Kk,
    const float* __restrict__ V, float* __restrict__ out)
{
    __shared__ unsigned long long keys[BUF];
    __shared__ int cut;
    __shared__ double d64s[KSEL];
    __shared__ __align__(16) float qs[DIM];

    const int q   = blockIdx.x;
    const int tid = threadIdx.x;
    const float qn = g_qn[q];

    if (tid == 0) cut = BUF;
    if (tid < DIM) qs[tid] = Q[(size_t)q * DIM + tid];

    const int cnt = min(g_cnt[q], CANDW);
    const unsigned long long* cand = g_cand + (size_t)q * CANDW;
    #pragma unroll
    for (int t = 0; t < BUF / 256; t++) {
        int i = tid + t * 256;
        keys[i] = (i < cnt) ? cand[i] : ~0ull;
    }
    __syncthreads();

    bitonic_sort_buf(keys, tid);

    // EPS cut around the approx 50th.
    {
        float d50 = __uint_as_float((unsigned)(keys[KSEL - 1] >> 32));
        unsigned cutbits = __float_as_uint(d50 + EPS);
        #pragma unroll
        for (int t = 0; t < BUF / 256; t++) {
            int i = tid + t * 256;
            if ((unsigned)(keys[i] >> 32) > cutbits) atomicMin(&cut, i);
        }
        __syncthreads();
    }
    const int M = min(cut, MMAX);

    // Exact bit-identical rescore: serial __fmaf_rn chain over k ascending,
    // single accumulator; d = fadd(fsub(qn, 2*dot), kn). (Defines selection.)
    {
        unsigned long long nk = ~0ull;
        if (tid < M) {
            unsigned idx = (unsigned)(keys[tid] & 0xFFFFFFFFu);
            const float4* kr = reinterpret_cast<const float4*>(Kk + (size_t)idx * DIM);
            const float4* qr = reinterpret_cast<const float4*>(qs);
            float acc = 0.f;
            #pragma unroll 8
            for (int j = 0; j < DIM / 4; j++) {
                float4 kv = __ldg(kr + j);
                float4 qv = qr[j];
                acc = __fmaf_rn(qv.x, kv.x, acc);
                acc = __fmaf_rn(qv.y, kv.y, acc);
                acc = __fmaf_rn(qv.z, kv.z, acc);
                acc = __fmaf_rn(qv.w, kv.w, acc);
            }
            float d = __fadd_rn(__fsub_rn(qn, __fmul_rn(2.f, acc)), g_kn[idx]);
            nk = ((unsigned long long)__float_as_uint(d) << 32) | idx;
        }
        __syncthreads();
        keys[tid] = nk;            // threads >= M write +INF sentinels
        __syncthreads();
        bitonic_sort256(keys, tid);
    }

    // fp64 rescore of the 50 winners (weights insensitive to this precision).
    const int lane = tid & 31;
    const int w    = tid >> 5;
    for (int j = w; j < KSEL; j += 8) {
        unsigned idx = (unsigned)(keys[j] & 0xFFFFFFFFu);
        float4 kv = reinterpret_cast<const float4*>(Kk + (size_t)idx * DIM)[lane];
        float4 qv = reinterpret_cast<const float4*>(qs)[lane];
        double dx = (double)qv.x - (double)kv.x;
        double dy = (double)qv.y - (double)kv.y;
        double dz = (double)qv.z - (double)kv.z;
        double dw = (double)qv.w - (double)kv.w;
        double s = dx * dx + dy * dy + dz * dz + dw * dw;
        #pragma unroll
        for (int o = 16; o; o >>= 1) s += __shfl_xor_sync(0xFFFFFFFFu, s, o);
        if (lane == 0) d64s[j] = s;
    }
    __syncthreads();

    if (tid == 0) {
        double usum = 0.0;
        #pragma unroll 1
        for (int j = 0; j < KSEL; j++) usum += 1.0 / (d64s[j] + (double)DELTA);
        double o = 0.0;
        #pragma unroll 1
        for (int j = 0; j < KSEL; j++) {
            unsigned idx = (unsigned)(keys[j] & 0xFFFFFFFFu);
            o += (1.0 / (d64s[j] + (double)DELTA)) / usum * (double)V[idx];
        }
        out[q] = (float)o;
    }
}

// ---------------------------------------------------------------------------
extern "C" void kernel_launch(void* const* d_in, const int* in_sizes, int n_in,
                              void* d_out, int out_size)
{
    const float* Q  = (const float*)d_in[0];   // [2048, 128]
    const float* Kk = (const float*)d_in[1];   // [100000, 128]
    const float* V  = (const float*)d_in[2];   // [100000]
    float* out      = (float*)d_out;           // [2048, 1]

    // K1: norms (bit-exact, strict serial-scalar reduce).
    int rows = NQ + NKP;
    norms_kernel<<<(rows + 255) / 256, 256>>>(Q, Kk);

    // K1b: bf16 split + counter zeroing.
    size_t elems = (size_t)(NQ + NKP) * DIM;
    prep_kernel<<<(int)((elems + 255) / 256), 256>>>(Q, Kk);

    // K2a: thr-pass GEMM over first NTHR keys.
    dim3 gthr(NTHR / 128, NQ / 128);           // (32, 16)
    gemm_thr_kernel<<<gthr, 256>>>();

    // K2b: per-query fixed thresholds.
    thr_kernel<<<NQ, 256>>>();

    // K2c: main fused GEMM + filter (no D matrix).
    dim3 g2(NKP / 128, NQ / 128);              // (782, 16)
    gemm_filter_kernel<<<g2, 256>>>();

    // K3: selection (candidate list -> exact rescore) + aggregation.
    select_kernel<<<NQ, 256>>>(Q, Kk, V, out);
}